// round 11
// baseline (speedup 1.0000x reference)
#include <cuda_runtime.h>
#include <cuda_fp16.h>
#include <cstdint>

// Problem constants
#define BATCH 4
#define HH 1080
#define WW 1920
#define NLUT 33
#define HW (HH * WW)                 // 2,073,600
#define PAIRS_PER (NLUT * NLUT * 32) // 34,848 half2 entries per (b,c)
#define NCOMBO 12                    // 4 batches * 3 channels
#define SMEM_BYTES (PAIRS_PER * 4)   // 139,392 B
#define SUBS 12                      // CTAs per combo
#define TPB 1024

__device__ __forceinline__ float tap(const __half2* __restrict__ sp,
                                     float x, float y, float z) {
    // __saturatef clamps to [0,1]; scale by 31.999998 (vs exact 32) so
    // i0 <= 31 always, keeping the +32 / +1056 / +1088 offsets in-bounds.
    // Trilinear interp is continuous across cell boundaries, so the 6e-8
    // relative coordinate perturbation is ~1e-6 in the output — far below
    // the table's fp16 quantization (~1e-4).
    float fx = __saturatef(x) * 31.999998f;
    float fy = __saturatef(y) * 31.999998f;
    float fz = __saturatef(z) * 31.999998f;
    int ix = (int)fx;
    int iy = (int)fy;
    int iz = (int)fz;
    float wx = fx - (float)ix;
    float wy = fy - (float)iy;
    float wz = fz - (float)iz;

    int base = (iz * NLUT + iy) * 32 + ix;
    __half2 q00 = sp[base];                  // (z0,y0): x0,x1 packed
    __half2 q01 = sp[base + 32];             // (z0,y1)
    __half2 q10 = sp[base + NLUT * 32];      // (z1,y0)
    __half2 q11 = sp[base + NLUT * 32 + 32]; // (z1,y1)

    float2 a00 = __half22float2(q00);
    float2 a01 = __half22float2(q01);
    float2 a10 = __half22float2(q10);
    float2 a11 = __half22float2(q11);

    float c00 = fmaf(wx, a00.y - a00.x, a00.x);
    float c01 = fmaf(wx, a01.y - a01.x, a01.x);
    float c10 = fmaf(wx, a10.y - a10.x, a10.x);
    float c11 = fmaf(wx, a11.y - a11.x, a11.x);
    float c0 = fmaf(wy, c01 - c00, c00);
    float c1 = fmaf(wy, c11 - c10, c10);
    return fmaf(wz, c1 - c0, c0);
}

__global__ void __launch_bounds__(TPB, 1)
lut_apply_kernel(const float* __restrict__ img,
                 const float* __restrict__ lut,
                 float* __restrict__ out) {
    extern __shared__ __half2 s_pairs[];
    const int combo = blockIdx.x % NCOMBO; // interleave: same-batch CTAs co-run (L2 reuse)
    const int sub = blockIdx.x / NCOMBO;   // 0..SUBS-1
    const int b = combo / 3;
    const int c = combo % 3;

    const float4* cx = reinterpret_cast<const float4*>(img + (size_t)b * 3 * HW);
    const float4* cy = cx + HW / 4;
    const float4* cz = cy + HW / 4;
    float4* o4 = reinterpret_cast<float4*>(out + (size_t)(b * 3 + c) * HW);

    const int npix4 = HW / 4;     // 518,400
    const int stride = SUBS * TPB;

    // Iteration 0's image loads first — their DRAM latency overlaps the
    // table build below.
    int p = sub * TPB + threadIdx.x;   // always < npix4
    float4 X = cx[p];
    float4 Y = cy[p];
    float4 Z = cz[p];

    // Build this combo's x-pair fp16 table directly from the fp32 lut
    // (fused; no separate build kernel, no global scratch).
    // s_pairs[((z*33 + y)*32 + x0)] = half2(lut[z][y][x0], lut[z][y][x0+1]).
    // idx = tid + k*TPB is warp-aligned, so x0 == lane and t = idx>>5 is
    // warp-uniform: one coalesced LDG covers lanes' lut[t*33 + lane]; the
    // x0+1 neighbor comes from shfl_down (lane 31 loads lut[t*33+32] itself).
    // KEPT ROLLED (#pragma unroll 1): unrolling this loop batches dozens of
    // LDGs, pins regs at the 64 cap, and wrecks the main loop (R10: 64 regs,
    // +4.9us kernel). Rolled, peak pressure stays at the main loop's ~51.
    {
        const float* lslice = lut + (size_t)combo * (NLUT * NLUT * NLUT);
        const int lane = threadIdx.x & 31;
#pragma unroll 1
        for (int k = 0; k < 35; k++) {
            int idx = threadIdx.x + k * TPB;
            if (idx < PAIRS_PER) {
                int t = idx >> 5;                 // z*33 + y (warp-uniform)
                float v0 = lslice[t * NLUT + lane];
                float v1 = __shfl_down_sync(0xFFFFFFFFu, v0, 1);
                if (lane == 31) v1 = lslice[t * NLUT + 32];
                s_pairs[idx] = __floats2half2_rn(v0, v1);
            }
        }
    }
    __syncthreads();

    // Software-pipelined main loop (unchanged — at its measured floor):
    // next iteration's global loads issue before this iteration's LDS-heavy
    // tap work consumes the current data. Taps stay in function form —
    // wider live ranges spill or thrash the 64-reg cap (R6/R8/R10).
#pragma unroll 1
    for (; p < npix4; p += stride) {
        int pn = min(p + stride, npix4 - 1);  // branchless prefetch guard
        float4 Xn = cx[pn];
        float4 Yn = cy[pn];
        float4 Zn = cz[pn];

        float4 R;
        R.x = tap(s_pairs, X.x, Y.x, Z.x);
        R.y = tap(s_pairs, X.y, Y.y, Z.y);
        R.z = tap(s_pairs, X.z, Y.z, Z.z);
        R.w = tap(s_pairs, X.w, Y.w, Z.w);
        o4[p] = R;

        X = Xn; Y = Yn; Z = Zn;
    }
}

extern "C" void kernel_launch(void* const* d_in, const int* in_sizes, int n_in,
                              void* d_out, int out_size) {
    const float* img = (const float*)d_in[0]; // (4,3,1080,1920) f32
    const float* lut = (const float*)d_in[1]; // (4,3,33,33,33) f32
    float* out = (float*)d_out;

    cudaFuncSetAttribute(lut_apply_kernel,
                         cudaFuncAttributeMaxDynamicSharedMemorySize, SMEM_BYTES);

    lut_apply_kernel<<<NCOMBO * SUBS, TPB, SMEM_BYTES>>>(img, lut, out);
}

// round 12
// speedup vs baseline: 1.1589x; 1.1589x over previous
#include <cuda_runtime.h>
#include <cuda_fp16.h>
#include <cstdint>

// Problem constants
#define BATCH 4
#define HH 1080
#define WW 1920
#define NLUT 33
#define HW (HH * WW)                 // 2,073,600
#define PAIRS_PER (NLUT * NLUT * 32) // 34,848 half2 entries per (b,c)
#define NCOMBO 12                    // 4 batches * 3 channels
#define SMEM_BYTES (PAIRS_PER * 4)   // 139,392 B
#define SUBS 12                      // CTAs per combo
#define TPB 1024

__device__ __forceinline__ float tap(const __half2* __restrict__ sp,
                                     float x, float y, float z) {
    // __saturatef clamps to [0,1]; scale by 31.999998 (vs exact 32) so
    // i0 <= 31 always, keeping the +32 / +1056 / +1088 offsets in-bounds.
    // Trilinear interp is continuous across cell boundaries, so the 6e-8
    // relative coordinate perturbation is ~1e-6 in the output — far below
    // the table's fp16 quantization (~1e-4).
    float fx = __saturatef(x) * 31.999998f;
    float fy = __saturatef(y) * 31.999998f;
    float fz = __saturatef(z) * 31.999998f;
    int ix = (int)fx;
    int iy = (int)fy;
    int iz = (int)fz;
    float wx = fx - (float)ix;
    float wy = fy - (float)iy;
    float wz = fz - (float)iz;

    int base = (iz * NLUT + iy) * 32 + ix;
    __half2 q00 = sp[base];                  // (z0,y0): x0,x1 packed
    __half2 q01 = sp[base + 32];             // (z0,y1)
    __half2 q10 = sp[base + NLUT * 32];      // (z1,y0)
    __half2 q11 = sp[base + NLUT * 32 + 32]; // (z1,y1)

    float2 a00 = __half22float2(q00);
    float2 a01 = __half22float2(q01);
    float2 a10 = __half22float2(q10);
    float2 a11 = __half22float2(q11);

    float c00 = fmaf(wx, a00.y - a00.x, a00.x);
    float c01 = fmaf(wx, a01.y - a01.x, a01.x);
    float c10 = fmaf(wx, a10.y - a10.x, a10.x);
    float c11 = fmaf(wx, a11.y - a11.x, a11.x);
    float c0 = fmaf(wy, c01 - c00, c00);
    float c1 = fmaf(wy, c11 - c10, c10);
    return fmaf(wz, c1 - c0, c0);
}

__global__ void __launch_bounds__(TPB, 1)
lut_apply_kernel(const float* __restrict__ img,
                 const float* __restrict__ lut,
                 float* __restrict__ out) {
    extern __shared__ __half2 s_pairs[];
    const int combo = blockIdx.x % NCOMBO; // interleave: same-batch CTAs co-run (L2 reuse)
    const int sub = blockIdx.x / NCOMBO;   // 0..SUBS-1
    const int b = combo / 3;
    const int c = combo % 3;

    const float4* cx = reinterpret_cast<const float4*>(img + (size_t)b * 3 * HW);
    const float4* cy = cx + HW / 4;
    const float4* cz = cy + HW / 4;
    float4* o4 = reinterpret_cast<float4*>(out + (size_t)(b * 3 + c) * HW);

    const int npix4 = HW / 4;     // 518,400
    const int stride = SUBS * TPB;

    // Iteration 0's image loads first — their DRAM latency overlaps the
    // table build below.
    int p = sub * TPB + threadIdx.x;   // always < npix4
    float4 X = cx[p];
    float4 Y = cy[p];
    float4 Z = cz[p];

    // Build this combo's x-pair fp16 table directly from the fp32 lut
    // (fused; no separate build kernel, no global scratch).
    // s_pairs[(z*33+y)*32 + x0] = half2(lut[z][y][x0], lut[z][y][x0+1]).
    // Each entry issues TWO INDEPENDENT LDGs (the +1 neighbor hits the same
    // L1 line) — no shfl, no dependent second load (R11's serialization bug).
    // MLP is bounded deliberately: inner 7 unrolled (14 loads in flight,
    // ~20 live regs — under the main loop's 51 so the register high-water
    // mark is untouched), outer 5 rolled (R10's full unroll hit the 64-reg
    // cap and wrecked the main loop).
    {
        const float* lslice = lut + (size_t)combo * (NLUT * NLUT * NLUT);
#pragma unroll 1
        for (int ko = 0; ko < 5; ko++) {
#pragma unroll
            for (int kj = 0; kj < 7; kj++) {
                int idx = threadIdx.x + (ko * 7 + kj) * TPB;
                if (idx < PAIRS_PER) {
                    int t = idx >> 5;     // z*33 + y
                    int x0 = idx & 31;
                    const float* row = lslice + t * NLUT + x0;
                    float v0 = row[0];
                    float v1 = row[1];
                    s_pairs[idx] = __floats2half2_rn(v0, v1);
                }
            }
        }
    }
    __syncthreads();

    // Software-pipelined main loop (unchanged — at its measured floor):
    // next iteration's global loads issue before this iteration's LDS-heavy
    // tap work consumes the current data. Taps stay in function form —
    // wider live ranges spill or thrash the 64-reg cap (R6/R8/R10).
#pragma unroll 1
    for (; p < npix4; p += stride) {
        int pn = min(p + stride, npix4 - 1);  // branchless prefetch guard
        float4 Xn = cx[pn];
        float4 Yn = cy[pn];
        float4 Zn = cz[pn];

        float4 R;
        R.x = tap(s_pairs, X.x, Y.x, Z.x);
        R.y = tap(s_pairs, X.y, Y.y, Z.y);
        R.z = tap(s_pairs, X.z, Y.z, Z.z);
        R.w = tap(s_pairs, X.w, Y.w, Z.w);
        o4[p] = R;

        X = Xn; Y = Yn; Z = Zn;
    }
}

extern "C" void kernel_launch(void* const* d_in, const int* in_sizes, int n_in,
                              void* d_out, int out_size) {
    const float* img = (const float*)d_in[0]; // (4,3,1080,1920) f32
    const float* lut = (const float*)d_in[1]; // (4,3,33,33,33) f32
    float* out = (float*)d_out;

    cudaFuncSetAttribute(lut_apply_kernel,
                         cudaFuncAttributeMaxDynamicSharedMemorySize, SMEM_BYTES);

    lut_apply_kernel<<<NCOMBO * SUBS, TPB, SMEM_BYTES>>>(img, lut, out);
}

// round 13
// speedup vs baseline: 1.2026x; 1.0377x over previous
#include <cuda_runtime.h>
#include <cuda_fp16.h>
#include <cstdint>

// Problem constants
#define BATCH 4
#define HH 1080
#define WW 1920
#define NLUT 33
#define HW (HH * WW)                 // 2,073,600
#define PAIRS_PER (NLUT * NLUT * 32) // 34,848 half2 entries per (b,c)
#define NQUADS (PAIRS_PER / 4)       // 8,712 16-byte quads
#define NCOMBO 12                    // 4 batches * 3 channels
#define SMEM_BYTES (PAIRS_PER * 4)   // 139,392 B
#define SUBS 12                      // CTAs per combo
#define TPB 1024

__device__ __forceinline__ float tap(const __half2* __restrict__ sp,
                                     float x, float y, float z) {
    // __saturatef clamps to [0,1]; scale by 31.999998 (vs exact 32) so
    // i0 <= 31 always, keeping the +32 / +1056 / +1088 offsets in-bounds.
    // Trilinear interp is continuous across cell boundaries, so the 6e-8
    // relative coordinate perturbation is ~1e-6 in the output — far below
    // the table's fp16 quantization (~1e-4).
    float fx = __saturatef(x) * 31.999998f;
    float fy = __saturatef(y) * 31.999998f;
    float fz = __saturatef(z) * 31.999998f;
    int ix = (int)fx;
    int iy = (int)fy;
    int iz = (int)fz;
    float wx = fx - (float)ix;
    float wy = fy - (float)iy;
    float wz = fz - (float)iz;

    int base = (iz * NLUT + iy) * 32 + ix;
    __half2 q00 = sp[base];                  // (z0,y0): x0,x1 packed
    __half2 q01 = sp[base + 32];             // (z0,y1)
    __half2 q10 = sp[base + NLUT * 32];      // (z1,y0)
    __half2 q11 = sp[base + NLUT * 32 + 32]; // (z1,y1)

    float2 a00 = __half22float2(q00);
    float2 a01 = __half22float2(q01);
    float2 a10 = __half22float2(q10);
    float2 a11 = __half22float2(q11);

    float c00 = fmaf(wx, a00.y - a00.x, a00.x);
    float c01 = fmaf(wx, a01.y - a01.x, a01.x);
    float c10 = fmaf(wx, a10.y - a10.x, a10.x);
    float c11 = fmaf(wx, a11.y - a11.x, a11.x);
    float c0 = fmaf(wy, c01 - c00, c00);
    float c1 = fmaf(wy, c11 - c10, c10);
    return fmaf(wz, c1 - c0, c0);
}

__global__ void __launch_bounds__(TPB, 1)
lut_apply_kernel(const float* __restrict__ img,
                 const float* __restrict__ lut,
                 float* __restrict__ out) {
    extern __shared__ __half2 s_pairs[];
    const int combo = blockIdx.x % NCOMBO; // interleave: same-batch CTAs co-run (L2 reuse)
    const int sub = blockIdx.x / NCOMBO;   // 0..SUBS-1
    const int b = combo / 3;
    const int c = combo % 3;

    const float4* cx = reinterpret_cast<const float4*>(img + (size_t)b * 3 * HW);
    const float4* cy = cx + HW / 4;
    const float4* cz = cy + HW / 4;
    float4* o4 = reinterpret_cast<float4*>(out + (size_t)(b * 3 + c) * HW);

    const int npix4 = HW / 4;     // 518,400
    const int stride = SUBS * TPB;

    // Iteration 0's image loads first — their DRAM latency overlaps the
    // table build below.
    int p = sub * TPB + threadIdx.x;   // always < npix4
    float4 X = cx[p];
    float4 Y = cy[p];
    float4 Z = cz[p];

    // Build this combo's x-pair fp16 table directly from the fp32 lut,
    // QUAD-vectorized: each iteration produces 4 consecutive pairs
    // (x0 = 4q..4q+3 of one row) from 5 scalar loads row[0..4] (the lut
    // row is 33 floats — unaligned for float4, but 5 independent LDG.32
    // hit 1-2 L1 lines) and commits them with ONE STS.128. Per 4 entries:
    // 5 LDG + 1 STS vs R12's 8 LDG + 4 STS (~2.5x fewer L1 wavefronts).
    // Pressure recipe per R10/R11/R12: inner 3 unrolled (15 loads in
    // flight, ~24 live regs < main loop's 51), outer 3 rolled.
    {
        const float* lslice = lut + (size_t)combo * (NLUT * NLUT * NLUT);
        uint4* dst = reinterpret_cast<uint4*>(s_pairs);
#pragma unroll 1
        for (int ko = 0; ko < 3; ko++) {
#pragma unroll
            for (int kj = 0; kj < 3; kj++) {
                int qi = threadIdx.x + (ko * 3 + kj) * TPB;
                if (qi < NQUADS) {
                    int t = qi >> 3;           // row = z*33 + y (8 quads/row)
                    int xq = (qi & 7) << 2;    // x0 = 0,4,...,28
                    const float* row = lslice + t * NLUT + xq;
                    float v0 = row[0];
                    float v1 = row[1];
                    float v2 = row[2];
                    float v3 = row[3];
                    float v4 = row[4];
                    union { __half2 h[4]; uint4 u; } pk;
                    pk.h[0] = __floats2half2_rn(v0, v1);
                    pk.h[1] = __floats2half2_rn(v1, v2);
                    pk.h[2] = __floats2half2_rn(v2, v3);
                    pk.h[3] = __floats2half2_rn(v3, v4);
                    dst[qi] = pk.u;
                }
            }
        }
    }
    __syncthreads();

    // Software-pipelined main loop (unchanged — at its measured floor):
    // next iteration's global loads issue before this iteration's LDS-heavy
    // tap work consumes the current data. Taps stay in function form —
    // wider live ranges spill or thrash the 64-reg cap (R6/R8/R10).
#pragma unroll 1
    for (; p < npix4; p += stride) {
        int pn = min(p + stride, npix4 - 1);  // branchless prefetch guard
        float4 Xn = cx[pn];
        float4 Yn = cy[pn];
        float4 Zn = cz[pn];

        float4 R;
        R.x = tap(s_pairs, X.x, Y.x, Z.x);
        R.y = tap(s_pairs, X.y, Y.y, Z.y);
        R.z = tap(s_pairs, X.z, Y.z, Z.z);
        R.w = tap(s_pairs, X.w, Y.w, Z.w);
        o4[p] = R;

        X = Xn; Y = Yn; Z = Zn;
    }
}

extern "C" void kernel_launch(void* const* d_in, const int* in_sizes, int n_in,
                              void* d_out, int out_size) {
    const float* img = (const float*)d_in[0]; // (4,3,1080,1920) f32
    const float* lut = (const float*)d_in[1]; // (4,3,33,33,33) f32
    float* out = (float*)d_out;

    cudaFuncSetAttribute(lut_apply_kernel,
                         cudaFuncAttributeMaxDynamicSharedMemorySize, SMEM_BYTES);

    lut_apply_kernel<<<NCOMBO * SUBS, TPB, SMEM_BYTES>>>(img, lut, out);
}